// round 5
// baseline (speedup 1.0000x reference)
#include <cuda_runtime.h>
#include <cuda_fp16.h>
#include <cstdint>

#define DEVI __device__ __forceinline__

static constexpr float BETA_C = 0.7f;
static constexpr float EPS_C  = 1e-8f;
static constexpr int   TILE_M = 128;

// per-item mu/alpha scratch (NUM_ITEMS = 100000)
__device__ float g_mu[100352];
__device__ float g_alpha[100352];

// ---------------- SMEM map (bytes) ----------------
// X    : 128 rows x 144B (64 f16 + 8 pad)          18432
// W1   : 64  rows x 272B (128 f16 + 8 pad)         17408
// W2HI : 128 rows x 272B                           34816
// W2LO : 128 rows x 272B                           34816
// HHI  : 128 rows x 272B                           34816
// HLO  : 128 rows x 272B                           34816
// B1/B2/W3 : 3 x 512B
#define SM_X     0
#define SM_W1    18432
#define SM_W2HI  35840
#define SM_W2LO  70656
#define SM_HHI   105472
#define SM_HLO   140288
#define SM_B1    175104
#define SM_B2    175616
#define SM_W3    176128
#define SM_TOTAL 176640

#define XSTRIDE  144
#define WSTRIDE  272

DEVI uint32_t smem_u32(const void* p) {
    uint32_t a;
    asm("{ .reg .u64 t; cvta.to.shared.u64 t, %1; cvt.u32.u64 %0, t; }" : "=r"(a) : "l"(p));
    return a;
}

#define LDSM_X4(r0, r1, r2, r3, addr)                                              \
    asm volatile("ldmatrix.sync.aligned.m8n8.x4.shared.b16 {%0,%1,%2,%3}, [%4];"   \
                 : "=r"(r0), "=r"(r1), "=r"(r2), "=r"(r3) : "r"(addr))

#define LDSM_X2T(r0, r1, addr)                                                     \
    asm volatile("ldmatrix.sync.aligned.m8n8.x2.trans.shared.b16 {%0,%1}, [%2];"   \
                 : "=r"(r0), "=r"(r1) : "r"(addr))

DEVI void mma16816(float* d, const uint32_t* a, uint32_t b0, uint32_t b1) {
    asm volatile(
        "mma.sync.aligned.m16n8k16.row.col.f32.f16.f16.f32 "
        "{%0,%1,%2,%3}, {%4,%5,%6,%7}, {%8,%9}, {%0,%1,%2,%3};"
        : "+f"(d[0]), "+f"(d[1]), "+f"(d[2]), "+f"(d[3])
        : "r"(a[0]), "r"(a[1]), "r"(a[2]), "r"(a[3]), "r"(b0), "r"(b1));
}

DEVI float softplus_f(float x) {
    return fmaxf(x, 0.0f) + __logf(1.0f + __expf(-fabsf(x)));
}

// =====================================================================
// Kernel 1: per-item MLPs via mma.sync (base -> g_mu, exc -> g_alpha)
// =====================================================================
__global__ __launch_bounds__(256)
void mlp_kernel(const float* __restrict__ emb, int nItems,
                const float* __restrict__ bW1, const float* __restrict__ bb1,
                const float* __restrict__ bW2, const float* __restrict__ bb2,
                const float* __restrict__ bW3,
                const float* __restrict__ eW1, const float* __restrict__ eb1,
                const float* __restrict__ eW2, const float* __restrict__ eb2,
                const float* __restrict__ eW3) {
    extern __shared__ char smem[];
    const uint32_t sb = smem_u32(smem);
    const int tid  = threadIdx.x;
    const int wid  = tid >> 5;
    const int lane = tid & 31;
    const int base = blockIdx.x * TILE_M;
    const int R0   = wid * 16;            // warp's 16-row tile

    // ---- load X tile (128 items x 64 dims), fp32 -> fp16, padded rows ----
    {
        const float4* emb4 = (const float4*)emb;
        for (int v = tid; v < 2048; v += 256) {
            int r = v >> 4, kq = v & 15;
            float4 f = make_float4(0.f, 0.f, 0.f, 0.f);
            int it = base + r;
            if (it < nItems) f = emb4[(size_t)it * 16 + kq];
            __half2 a = __floats2half2_rn(f.x, f.y);
            __half2 b = __floats2half2_rn(f.z, f.w);
            *reinterpret_cast<uint2*>(smem + SM_X + r * XSTRIDE + kq * 8) =
                make_uint2(*reinterpret_cast<uint32_t*>(&a), *reinterpret_cast<uint32_t*>(&b));
        }
    }

    // per-thread ldmatrix address components
    const int arow = lane & 15;           // row within 16-row tile
    const int acol = (lane >> 4) * 16;    // byte offset of k-half (0 or 16B)

    for (int mlp = 0; mlp < 2; ++mlp) {
        const float* W1 = mlp ? eW1 : bW1;
        const float* b1 = mlp ? eb1 : bb1;
        const float* W2 = mlp ? eW2 : bW2;
        const float* b2 = mlp ? eb2 : bb2;
        const float* W3 = mlp ? eW3 : bW3;

        __syncthreads();   // protect weight smem from previous iteration readers

        // ---- W1 [64 x 128] fp32 -> f16 (rows padded) ----
        {
            const float4* w4 = (const float4*)W1;
            for (int v = tid; v < 2048; v += 256) {
                int k = v >> 5, nq = v & 31;
                float4 f = w4[v];
                __half2 a = __floats2half2_rn(f.x, f.y);
                __half2 b = __floats2half2_rn(f.z, f.w);
                *reinterpret_cast<uint2*>(smem + SM_W1 + k * WSTRIDE + nq * 8) =
                    make_uint2(*reinterpret_cast<uint32_t*>(&a), *reinterpret_cast<uint32_t*>(&b));
            }
        }
        // ---- W2 [128 x 128] fp32 -> hi/lo f16 ----
        {
            const float4* w4 = (const float4*)W2;
            for (int v = tid; v < 4096; v += 256) {
                int k = v >> 5, nq = v & 31;
                float4 f = w4[v];
                __half hx = __float2half_rn(f.x), hy = __float2half_rn(f.y);
                __half hz = __float2half_rn(f.z), hw = __float2half_rn(f.w);
                __half lx = __float2half_rn(f.x - __half2float(hx));
                __half ly = __float2half_rn(f.y - __half2float(hy));
                __half lz = __float2half_rn(f.z - __half2float(hz));
                __half lw = __float2half_rn(f.w - __half2float(hw));
                __half2 ha = __halves2half2(hx, hy), hb = __halves2half2(hz, hw);
                __half2 la = __halves2half2(lx, ly), lb = __halves2half2(lz, lw);
                int off = k * WSTRIDE + nq * 8;
                *reinterpret_cast<uint2*>(smem + SM_W2HI + off) =
                    make_uint2(*reinterpret_cast<uint32_t*>(&ha), *reinterpret_cast<uint32_t*>(&hb));
                *reinterpret_cast<uint2*>(smem + SM_W2LO + off) =
                    make_uint2(*reinterpret_cast<uint32_t*>(&la), *reinterpret_cast<uint32_t*>(&lb));
            }
        }
        if (tid < 128) {
            ((float*)(smem + SM_B1))[tid] = b1[tid];
            ((float*)(smem + SM_B2))[tid] = b2[tid];
            ((float*)(smem + SM_W3))[tid] = W3[tid];
        }
        __syncthreads();

        // ================= Layer 1: H1 = softplus(X @ W1 + b1) =================
        {
            float acc[64];
#pragma unroll
            for (int i = 0; i < 64; ++i) acc[i] = 0.f;

            uint32_t afr[4][4];
#pragma unroll
            for (int kt = 0; kt < 4; ++kt) {
                uint32_t addr = sb + SM_X + (R0 + arow) * XSTRIDE + kt * 32 + acol;
                LDSM_X4(afr[kt][0], afr[kt][1], afr[kt][2], afr[kt][3], addr);
            }
#pragma unroll
            for (int kt = 0; kt < 4; ++kt) {
                uint32_t brow = sb + SM_W1 + (kt * 16 + arow) * WSTRIDE;
#pragma unroll
                for (int nt = 0; nt < 16; ++nt) {
                    uint32_t b0, b1r;
                    LDSM_X2T(b0, b1r, brow + nt * 16);
                    mma16816(acc + nt * 4, afr[kt], b0, b1r);
                }
            }

            // epilogue 1: softplus, split hi/lo, write to H smem
            const float* b1s = (const float*)(smem + SM_B1);
            const int rr  = R0 + (lane >> 2);
            const int cc0 = 2 * (lane & 3);
#pragma unroll
            for (int nt = 0; nt < 16; ++nt) {
                int col = nt * 8 + cc0;
#pragma unroll
                for (int h = 0; h < 2; ++h) {   // h=0: row rr, h=1: row rr+8
                    float x0 = acc[nt * 4 + 2 * h + 0] + b1s[col];
                    float x1 = acc[nt * 4 + 2 * h + 1] + b1s[col + 1];
                    float h0 = softplus_f(x0), h1 = softplus_f(x1);
                    __half a0 = __float2half_rn(h0), a1 = __float2half_rn(h1);
                    __half l0 = __float2half_rn(h0 - __half2float(a0));
                    __half l1 = __float2half_rn(h1 - __half2float(a1));
                    __half2 hh = __halves2half2(a0, a1);
                    __half2 ll = __halves2half2(l0, l1);
                    int off = (rr + h * 8) * WSTRIDE + col * 2;
                    *reinterpret_cast<uint32_t*>(smem + SM_HHI + off) =
                        *reinterpret_cast<uint32_t*>(&hh);
                    *reinterpret_cast<uint32_t*>(smem + SM_HLO + off) =
                        *reinterpret_cast<uint32_t*>(&ll);
                }
            }
            __syncwarp();   // warp reads back only its own 16 rows
        }

        // ====== Layer 2: Y2 = Hhi@W2hi + Hhi@W2lo + Hlo@W2hi (K=128) ======
        {
            float acc[64];
#pragma unroll
            for (int i = 0; i < 64; ++i) acc[i] = 0.f;

            uint32_t ahi[8][4];
#pragma unroll
            for (int kt = 0; kt < 8; ++kt) {
                uint32_t addr = sb + SM_HHI + (R0 + arow) * WSTRIDE + kt * 32 + acol;
                LDSM_X4(ahi[kt][0], ahi[kt][1], ahi[kt][2], ahi[kt][3], addr);
            }
            // pass 0: Hhi @ W2hi
#pragma unroll
            for (int kt = 0; kt < 8; ++kt) {
                uint32_t brow = sb + SM_W2HI + (kt * 16 + arow) * WSTRIDE;
#pragma unroll
                for (int nt = 0; nt < 16; ++nt) {
                    uint32_t b0, b1r;
                    LDSM_X2T(b0, b1r, brow + nt * 16);
                    mma16816(acc + nt * 4, ahi[kt], b0, b1r);
                }
            }
            // pass 1: Hhi @ W2lo
#pragma unroll
            for (int kt = 0; kt < 8; ++kt) {
                uint32_t brow = sb + SM_W2LO + (kt * 16 + arow) * WSTRIDE;
#pragma unroll
                for (int nt = 0; nt < 16; ++nt) {
                    uint32_t b0, b1r;
                    LDSM_X2T(b0, b1r, brow + nt * 16);
                    mma16816(acc + nt * 4, ahi[kt], b0, b1r);
                }
            }
            // pass 2: Hlo @ W2hi
#pragma unroll
            for (int kt = 0; kt < 8; ++kt) {
                uint32_t alo[4];
                uint32_t addr = sb + SM_HLO + (R0 + arow) * WSTRIDE + kt * 32 + acol;
                LDSM_X4(alo[0], alo[1], alo[2], alo[3], addr);
                uint32_t brow = sb + SM_W2HI + (kt * 16 + arow) * WSTRIDE;
#pragma unroll
                for (int nt = 0; nt < 16; ++nt) {
                    uint32_t b0, b1r;
                    LDSM_X2T(b0, b1r, brow + nt * 16);
                    mma16816(acc + nt * 4, alo, b0, b1r);
                }
            }

            // epilogue 2: y3 = sum softplus(y2+b2)*W3 ; out = softplus(y3)+eps
            const float* b2s = (const float*)(smem + SM_B2);
            const float* w3s = (const float*)(smem + SM_W3);
            const int cc0 = 2 * (lane & 3);
            float s0 = 0.f, s1 = 0.f;
#pragma unroll
            for (int nt = 0; nt < 16; ++nt) {
                int col = nt * 8 + cc0;
                s0 += softplus_f(acc[nt * 4 + 0] + b2s[col])     * w3s[col];
                s0 += softplus_f(acc[nt * 4 + 1] + b2s[col + 1]) * w3s[col + 1];
                s1 += softplus_f(acc[nt * 4 + 2] + b2s[col])     * w3s[col];
                s1 += softplus_f(acc[nt * 4 + 3] + b2s[col + 1]) * w3s[col + 1];
            }
            s0 += __shfl_xor_sync(0xffffffffu, s0, 1);
            s0 += __shfl_xor_sync(0xffffffffu, s0, 2);
            s1 += __shfl_xor_sync(0xffffffffu, s1, 1);
            s1 += __shfl_xor_sync(0xffffffffu, s1, 2);
            if ((lane & 3) == 0) {
                int g  = lane >> 2;
                float* dst = mlp ? g_alpha : g_mu;
                int it0 = base + R0 + g;
                int it1 = it0 + 8;
                if (it0 < nItems) dst[it0] = softplus_f(s0) + EPS_C;
                if (it1 < nItems) dst[it1] = softplus_f(s1) + EPS_C;
            }
        }
    }
}

// =====================================================================
// Kernel 2: Hawkes reduction + combine. 8 lanes per candidate, float4 loads.
// =====================================================================
__global__ __launch_bounds__(256)
void score_kernel(const int* __restrict__ items, const float* __restrict__ qt,
                  const float* __restrict__ hist, int BC, int Cc, int L,
                  float* __restrict__ out) {
    const int warp = threadIdx.x >> 5, lane = threadIdx.x & 31;
    const int grp = lane >> 3, sub = lane & 7;
    const int cand = blockIdx.x * 32 + warp * 4 + grp;

    float s = 0.f;
    if (cand < BC) {
        const int b = cand / Cc;
        const float q = __ldg(&qt[b]);
        const float4* hp = (const float4*)(hist + (size_t)cand * L);
        const int n4 = L >> 2;
        for (int i = sub; i < n4; i += 8) {
            float4 t = hp[i];
            float d0 = t.x - q, d1 = t.y - q, d2 = t.z - q, d3 = t.w - q;
            s += (d0 < 0.f) ? __expf(BETA_C * d0) : 0.f;
            s += (d1 < 0.f) ? __expf(BETA_C * d1) : 0.f;
            s += (d2 < 0.f) ? __expf(BETA_C * d2) : 0.f;
            s += (d3 < 0.f) ? __expf(BETA_C * d3) : 0.f;
        }
        for (int l = (n4 << 2) + sub; l < L; l += 8) {   // tail (L%4 != 0)
            float d = hist[(size_t)cand * L + l] - q;
            s += (d < 0.f) ? __expf(BETA_C * d) : 0.f;
        }
    }
    s += __shfl_xor_sync(0xffffffffu, s, 1);
    s += __shfl_xor_sync(0xffffffffu, s, 2);
    s += __shfl_xor_sync(0xffffffffu, s, 4);
    if (cand < BC && sub == 0) {
        int it = items[cand];
        out[cand] = g_mu[it] + g_alpha[it] * s;
    }
}

// =====================================================================
extern "C" void kernel_launch(void* const* d_in, const int* in_sizes, int n_in,
                              void* d_out, int out_size) {
    const int*   items = (const int*)d_in[0];
    const float* qt    = (const float*)d_in[1];
    const float* hist  = (const float*)d_in[2];
    const float* emb   = (const float*)d_in[3];
    const float* bW1 = (const float*)d_in[4];
    const float* bb1 = (const float*)d_in[5];
    const float* bW2 = (const float*)d_in[6];
    const float* bb2 = (const float*)d_in[7];
    const float* bW3 = (const float*)d_in[8];
    const float* eW1 = (const float*)d_in[9];
    const float* eb1 = (const float*)d_in[10];
    const float* eW2 = (const float*)d_in[11];
    const float* eb2 = (const float*)d_in[12];
    const float* eW3 = (const float*)d_in[13];

    const int BC     = in_sizes[0];
    const int Bn     = in_sizes[1];
    const int Cc     = BC / Bn;
    const int L      = in_sizes[2] / BC;
    const int nItems = in_sizes[3] / 64;

    float* out = (float*)d_out;

    cudaFuncSetAttribute(mlp_kernel, cudaFuncAttributeMaxDynamicSharedMemorySize, SM_TOTAL);

    const int tiles = (nItems + TILE_M - 1) / TILE_M;
    mlp_kernel<<<tiles, 256, SM_TOTAL>>>(emb, nItems, bW1, bb1, bW2, bb2, bW3,
                                         eW1, eb1, eW2, eb2, eW3);

    const int blocks = (BC + 31) / 32;
    score_kernel<<<blocks, 256>>>(items, qt, hist, BC, Cc, L, out);
    (void)n_in; (void)out_size;
}

// round 8
// speedup vs baseline: 1.9313x; 1.9313x over previous
#include <cuda_runtime.h>
#include <cuda_fp16.h>
#include <cstdint>

#define DEVI __device__ __forceinline__

static constexpr float BETA_C = 0.7f;
static constexpr float EPS_C  = 1e-8f;
static constexpr int   TILE_M = 128;
static constexpr float HC     = 0.69140625f;   // centering const, exact in fp16

// per-item mu/alpha scratch (NUM_ITEMS = 100000)
__device__ float g_mu[100352];
__device__ float g_alpha[100352];

// ---------------- SMEM map (bytes) ----------------
// X  : 128 x 144B (64 f16 + pad)     18432   \  aliased by
// W1 : 64  x 272B (128 f16 + pad)    17408   /  HC: 128 x 272B (34816)
// W2 : 128 x 272B                    34816
#define SM_X     0
#define SM_W1    18432
#define SM_HC    0
#define SM_W2    35840
#define SM_B1    70656
#define SM_FB2   71168
#define SM_W3    71680
#define SM_CSP   72192
#define SM_RED   73216
#define SM_TOTAL 75264

#define XSTRIDE  144
#define WSTRIDE  272

DEVI uint32_t smem_u32(const void* p) {
    uint32_t a;
    asm("{ .reg .u64 t; cvta.to.shared.u64 t, %1; cvt.u32.u64 %0, t; }" : "=r"(a) : "l"(p));
    return a;
}

#define LDSM_X4(r0, r1, r2, r3, addr)                                              \
    asm volatile("ldmatrix.sync.aligned.m8n8.x4.shared.b16 {%0,%1,%2,%3}, [%4];"   \
                 : "=r"(r0), "=r"(r1), "=r"(r2), "=r"(r3) : "r"(addr))

#define LDSM_X4T(r0, r1, r2, r3, addr)                                             \
    asm volatile("ldmatrix.sync.aligned.m8n8.x4.trans.shared.b16 {%0,%1,%2,%3}, [%4];" \
                 : "=r"(r0), "=r"(r1), "=r"(r2), "=r"(r3) : "r"(addr))

DEVI void mma16816(float* d, const uint32_t* a, uint32_t b0, uint32_t b1) {
    asm volatile(
        "mma.sync.aligned.m16n8k16.row.col.f32.f16.f16.f32 "
        "{%0,%1,%2,%3}, {%4,%5,%6,%7}, {%8,%9}, {%0,%1,%2,%3};"
        : "+f"(d[0]), "+f"(d[1]), "+f"(d[2]), "+f"(d[3])
        : "r"(a[0]), "r"(a[1]), "r"(a[2]), "r"(a[3]), "r"(b0), "r"(b1));
}

DEVI float softplus_f(float x) {
    return fmaxf(x, 0.0f) + __logf(1.0f + __expf(-fabsf(x)));
}

// =====================================================================
// Kernel 1: per-item MLPs via mma.sync (base -> g_mu, exc -> g_alpha)
// warp tile = 64 rows x 32 cols; single-pass fp16 with centering comp.
// =====================================================================
__global__ __launch_bounds__(256, 2)
void mlp_kernel(const float* __restrict__ emb, int nItems,
                const float* __restrict__ bW1, const float* __restrict__ bb1,
                const float* __restrict__ bW2, const float* __restrict__ bb2,
                const float* __restrict__ bW3,
                const float* __restrict__ eW1, const float* __restrict__ eb1,
                const float* __restrict__ eW2, const float* __restrict__ eb2,
                const float* __restrict__ eW3) {
    extern __shared__ char smem[];
    const uint32_t sb = smem_u32(smem);
    const int tid  = threadIdx.x;
    const int wid  = tid >> 5;
    const int lane = tid & 31;
    const int base = blockIdx.x * TILE_M;
    const int rg   = wid >> 2;          // row group: rows rg*64 .. +64
    const int cg   = wid & 3;           // col group: cols cg*32 .. +32

    // ldmatrix addressing
    const int arow = lane & 15;
    const int acol = (lane >> 4) * 16;
    const int brow = (lane & 7) + ((lane >> 3) & 1) * 8;  // k within 16-block
    const int bcol = ((lane >> 4) & 1) * 8;               // +8 cols for tiles 2,3

    for (int mlp = 0; mlp < 2; ++mlp) {
        const float* W1 = mlp ? eW1 : bW1;
        const float* b1 = mlp ? eb1 : bb1;
        const float* W2 = mlp ? eW2 : bW2;
        const float* b2 = mlp ? eb2 : bb2;
        const float* W3 = mlp ? eW3 : bW3;

        __syncthreads();   // previous iteration's smem readers done

        // ---- fill X (128 items x 64 dims) fp16, padded rows ----
        {
            const float4* emb4 = (const float4*)emb;
            for (int v = tid; v < 2048; v += 256) {
                int r = v >> 4, kq = v & 15;
                float4 f = make_float4(0.f, 0.f, 0.f, 0.f);
                int it = base + r;
                if (it < nItems) f = emb4[(size_t)it * 16 + kq];
                __half2 a = __floats2half2_rn(f.x, f.y);
                __half2 b = __floats2half2_rn(f.z, f.w);
                *reinterpret_cast<uint2*>(smem + SM_X + r * XSTRIDE + kq * 8) =
                    make_uint2(*reinterpret_cast<uint32_t*>(&a), *reinterpret_cast<uint32_t*>(&b));
            }
        }
        // ---- fill W1 [64 x 128] fp16 ----
        {
            const float4* w4 = (const float4*)W1;
            for (int v = tid; v < 2048; v += 256) {
                int k = v >> 5, nq = v & 31;
                float4 f = w4[v];
                __half2 a = __floats2half2_rn(f.x, f.y);
                __half2 b = __floats2half2_rn(f.z, f.w);
                *reinterpret_cast<uint2*>(smem + SM_W1 + k * WSTRIDE + nq * 8) =
                    make_uint2(*reinterpret_cast<uint32_t*>(&a), *reinterpret_cast<uint32_t*>(&b));
            }
        }
        // ---- fill W2 [128 x 128] fp16 ----
        {
            const float4* w4 = (const float4*)W2;
            for (int v = tid; v < 4096; v += 256) {
                int k = v >> 5, nq = v & 31;
                float4 f = w4[v];
                __half2 a = __floats2half2_rn(f.x, f.y);
                __half2 b = __floats2half2_rn(f.z, f.w);
                *reinterpret_cast<uint2*>(smem + SM_W2 + k * WSTRIDE + nq * 8) =
                    make_uint2(*reinterpret_cast<uint32_t*>(&a), *reinterpret_cast<uint32_t*>(&b));
            }
        }
        if (tid < 128) {
            ((float*)(smem + SM_B1))[tid] = b1[tid];
            ((float*)(smem + SM_W3))[tid] = W3[tid];
        }
        // ---- fp32 column sums of W2 (for centering compensation) ----
        {
            int j = tid & 127, kh = tid >> 7;
            float cs = 0.f;
            const float* wp = W2 + (size_t)(kh * 64) * 128 + j;
#pragma unroll 8
            for (int k = 0; k < 64; ++k) cs += wp[(size_t)k * 128];
            ((float*)(smem + SM_CSP))[kh * 128 + j] = cs;
        }
        __syncthreads();

        if (tid < 128) {
            const float* csp = (const float*)(smem + SM_CSP);
            ((float*)(smem + SM_FB2))[tid] = HC * (csp[tid] + csp[128 + tid]) + b2[tid];
        }

        // ================= Layer 1: Hc = softplus(X@W1 + b1) - HC =================
        float acc[64];
#pragma unroll
        for (int i = 0; i < 64; ++i) acc[i] = 0.f;
        {
            uint32_t bw[2][4][4];
#pragma unroll
            for (int nt2 = 0; nt2 < 2; ++nt2)
#pragma unroll
                for (int kt = 0; kt < 4; ++kt) {
                    uint32_t a = sb + SM_W1 + (kt * 16 + brow) * WSTRIDE +
                                 (cg * 32 + nt2 * 16 + bcol) * 2;
                    LDSM_X4T(bw[nt2][kt][0], bw[nt2][kt][1], bw[nt2][kt][2], bw[nt2][kt][3], a);
                }
#pragma unroll
            for (int mt = 0; mt < 4; ++mt) {
                uint32_t afr[4][4];
#pragma unroll
                for (int kt = 0; kt < 4; ++kt) {
                    uint32_t a = sb + SM_X + (rg * 64 + mt * 16 + arow) * XSTRIDE + kt * 32 + acol;
                    LDSM_X4(afr[kt][0], afr[kt][1], afr[kt][2], afr[kt][3], a);
                }
#pragma unroll
                for (int nt2 = 0; nt2 < 2; ++nt2)
#pragma unroll
                    for (int kt = 0; kt < 4; ++kt) {
                        mma16816(acc + (mt * 4 + nt2 * 2) * 4,     afr[kt], bw[nt2][kt][0], bw[nt2][kt][1]);
                        mma16816(acc + (mt * 4 + nt2 * 2 + 1) * 4, afr[kt], bw[nt2][kt][2], bw[nt2][kt][3]);
                    }
            }
        }
        // epilogue 1 (compute in regs, store after barrier)
        uint32_t hreg[32];
        {
            const float* b1s = (const float*)(smem + SM_B1);
            const int cc0 = 2 * (lane & 3);
#pragma unroll
            for (int mt = 0; mt < 4; ++mt)
#pragma unroll
                for (int nt = 0; nt < 4; ++nt) {
                    int col = cg * 32 + nt * 8 + cc0;
                    float bb0 = b1s[col], bb1v = b1s[col + 1];
#pragma unroll
                    for (int h = 0; h < 2; ++h) {
                        float x0 = acc[(mt * 4 + nt) * 4 + 2 * h + 0] + bb0;
                        float x1 = acc[(mt * 4 + nt) * 4 + 2 * h + 1] + bb1v;
                        __half2 hh = __floats2half2_rn(softplus_f(x0) - HC,
                                                       softplus_f(x1) - HC);
                        hreg[(mt * 4 + nt) * 2 + h] = *reinterpret_cast<uint32_t*>(&hh);
                    }
                }
        }
        __syncthreads();   // all warps finished reading X/W1 (aliased by HC)
        {
            const int rr  = lane >> 2;
            const int cc0 = 2 * (lane & 3);
#pragma unroll
            for (int mt = 0; mt < 4; ++mt)
#pragma unroll
                for (int nt = 0; nt < 4; ++nt)
#pragma unroll
                    for (int h = 0; h < 2; ++h) {
                        int row = rg * 64 + mt * 16 + rr + 8 * h;
                        int col = cg * 32 + nt * 8 + cc0;
                        *reinterpret_cast<uint32_t*>(smem + SM_HC + row * WSTRIDE + col * 2) =
                            hreg[(mt * 4 + nt) * 2 + h];
                    }
        }
        __syncthreads();

        // ====== Layer 2: Y2 = Hc @ W2 (K=128), comp via FB2 ======
#pragma unroll
        for (int i = 0; i < 64; ++i) acc[i] = 0.f;
#pragma unroll
        for (int kb = 0; kb < 2; ++kb) {
            uint32_t bw[2][4][4];
#pragma unroll
            for (int nt2 = 0; nt2 < 2; ++nt2)
#pragma unroll
                for (int kt = 0; kt < 4; ++kt) {
                    uint32_t a = sb + SM_W2 + (kb * 64 + kt * 16 + brow) * WSTRIDE +
                                 (cg * 32 + nt2 * 16 + bcol) * 2;
                    LDSM_X4T(bw[nt2][kt][0], bw[nt2][kt][1], bw[nt2][kt][2], bw[nt2][kt][3], a);
                }
#pragma unroll
            for (int mt = 0; mt < 4; ++mt) {
                uint32_t afr[4][4];
#pragma unroll
                for (int kt = 0; kt < 4; ++kt) {
                    uint32_t a = sb + SM_HC + (rg * 64 + mt * 16 + arow) * WSTRIDE +
                                 kb * 128 + kt * 32 + acol;
                    LDSM_X4(afr[kt][0], afr[kt][1], afr[kt][2], afr[kt][3], a);
                }
#pragma unroll
                for (int nt2 = 0; nt2 < 2; ++nt2)
#pragma unroll
                    for (int kt = 0; kt < 4; ++kt) {
                        mma16816(acc + (mt * 4 + nt2 * 2) * 4,     afr[kt], bw[nt2][kt][0], bw[nt2][kt][1]);
                        mma16816(acc + (mt * 4 + nt2 * 2 + 1) * 4, afr[kt], bw[nt2][kt][2], bw[nt2][kt][3]);
                    }
            }
        }
        // epilogue 2: row partials of sum softplus(y2)*W3
        {
            const float* fb2 = (const float*)(smem + SM_FB2);
            const float* w3s = (const float*)(smem + SM_W3);
            const int cc0 = 2 * (lane & 3);
            float s[4][2];
#pragma unroll
            for (int mt = 0; mt < 4; ++mt) { s[mt][0] = 0.f; s[mt][1] = 0.f; }
#pragma unroll
            for (int mt = 0; mt < 4; ++mt)
#pragma unroll
                for (int nt = 0; nt < 4; ++nt) {
                    int col = cg * 32 + nt * 8 + cc0;
                    float f0 = fb2[col], f1 = fb2[col + 1];
                    float w0 = w3s[col], w1 = w3s[col + 1];
#pragma unroll
                    for (int h = 0; h < 2; ++h) {
                        float y0 = acc[(mt * 4 + nt) * 4 + 2 * h + 0] + f0;
                        float y1 = acc[(mt * 4 + nt) * 4 + 2 * h + 1] + f1;
                        s[mt][h] += softplus_f(y0) * w0 + softplus_f(y1) * w1;
                    }
                }
#pragma unroll
            for (int mt = 0; mt < 4; ++mt)
#pragma unroll
                for (int h = 0; h < 2; ++h) {
                    s[mt][h] += __shfl_xor_sync(0xffffffffu, s[mt][h], 1);
                    s[mt][h] += __shfl_xor_sync(0xffffffffu, s[mt][h], 2);
                }
            float* red = (float*)(smem + SM_RED);
            if ((lane & 3) == 0) {
#pragma unroll
                for (int mt = 0; mt < 4; ++mt)
#pragma unroll
                    for (int h = 0; h < 2; ++h) {
                        int lrow = rg * 64 + mt * 16 + (lane >> 2) + 8 * h;
                        red[lrow * 4 + cg] = s[mt][h];
                    }
            }
            __syncthreads();
            if (tid < 128) {
                float y3 = red[tid * 4 + 0] + red[tid * 4 + 1] +
                           red[tid * 4 + 2] + red[tid * 4 + 3];
                int it = base + tid;
                if (it < nItems) (mlp ? g_alpha : g_mu)[it] = softplus_f(y3) + EPS_C;
            }
        }
    }
}

// =====================================================================
// Kernel 2: Hawkes reduction + combine. 8 lanes per candidate, float4 loads.
// exp(beta*(t-q)) factored as exp(beta*t) * exp(-beta*q).
// =====================================================================
__global__ __launch_bounds__(256)
void score_kernel(const int* __restrict__ items, const float* __restrict__ qt,
                  const float* __restrict__ hist, int BC, int Cc, int L,
                  float* __restrict__ out) {
    const int warp = threadIdx.x >> 5, lane = threadIdx.x & 31;
    const int grp = lane >> 3, sub = lane & 7;
    const int cand = blockIdx.x * 32 + warp * 4 + grp;

    float s = 0.f;
    float q = 0.f;
    if (cand < BC) {
        const int b = cand / Cc;
        q = __ldg(&qt[b]);
        const float4* hp = (const float4*)(hist + (size_t)cand * L);
        const int n4 = L >> 2;
        for (int i = sub; i < n4; i += 8) {
            float4 t = hp[i];
            s += (t.x < q) ? __expf(BETA_C * t.x) : 0.f;
            s += (t.y < q) ? __expf(BETA_C * t.y) : 0.f;
            s += (t.z < q) ? __expf(BETA_C * t.z) : 0.f;
            s += (t.w < q) ? __expf(BETA_C * t.w) : 0.f;
        }
        for (int l = (n4 << 2) + sub; l < L; l += 8) {
            float t = hist[(size_t)cand * L + l];
            s += (t < q) ? __expf(BETA_C * t) : 0.f;
        }
    }
    s += __shfl_xor_sync(0xffffffffu, s, 1);
    s += __shfl_xor_sync(0xffffffffu, s, 2);
    s += __shfl_xor_sync(0xffffffffu, s, 4);
    if (cand < BC && sub == 0) {
        int it = items[cand];
        out[cand] = g_mu[it] + g_alpha[it] * (s * __expf(-BETA_C * q));
    }
}

// =====================================================================
extern "C" void kernel_launch(void* const* d_in, const int* in_sizes, int n_in,
                              void* d_out, int out_size) {
    const int*   items = (const int*)d_in[0];
    const float* qt    = (const float*)d_in[1];
    const float* hist  = (const float*)d_in[2];
    const float* emb   = (const float*)d_in[3];
    const float* bW1 = (const float*)d_in[4];
    const float* bb1 = (const float*)d_in[5];
    const float* bW2 = (const float*)d_in[6];
    const float* bb2 = (const float*)d_in[7];
    const float* bW3 = (const float*)d_in[8];
    const float* eW1 = (const float*)d_in[9];
    const float* eb1 = (const float*)d_in[10];
    const float* eW2 = (const float*)d_in[11];
    const float* eb2 = (const float*)d_in[12];
    const float* eW3 = (const float*)d_in[13];

    const int BC     = in_sizes[0];
    const int Bn     = in_sizes[1];
    const int Cc     = BC / Bn;
    const int L      = in_sizes[2] / BC;
    const int nItems = in_sizes[3] / 64;

    float* out = (float*)d_out;

    cudaFuncSetAttribute(mlp_kernel, cudaFuncAttributeMaxDynamicSharedMemorySize, SM_TOTAL);

    const int tiles = (nItems + TILE_M - 1) / TILE_M;
    mlp_kernel<<<tiles, 256, SM_TOTAL>>>(emb, nItems, bW1, bb1, bW2, bb2, bW3,
                                         eW1, eb1, eW2, eb2, eW3);

    const int blocks = (BC + 31) / 32;
    score_kernel<<<blocks, 256>>>(items, qt, hist, BC, Cc, L, out);
    (void)n_in; (void)out_size;
}